// round 2
// baseline (speedup 1.0000x reference)
#include <cuda_runtime.h>
#include <math.h>

// Signature-kernel MMD on GB300.
// Shapes: X, Y: (64, 128, 16) fp32. n = 0 (f = 1). Output: scalar fp32.
//
// Per pair (a,b): inc = dX_a @ dY_b^T (127x127, K=16), then Goursat DP:
//   G[i][j] = G[i][j-1] + G[i-1][j] + G[i-1][j-1]*(inc[i-1][j-1]-1), G row0/col0 = 1.
// k(a,b) = G[127][127].  Loss = mean kxx + mean kyy - 2 mean kxy.
// XX / YY are symmetric: compute upper triangle with weight 2 off-diagonal.

#define DIM   16
#define NSEQ  127     // number of increments
#define NTRI  2080    // 64*65/2
#define NTASK 8256    // 2*NTRI + 4096

__device__ double g_acc;

__global__ void sig_init() { g_acc = 0.0; }
__global__ void sig_fin(float* out) { out[0] = (float)g_acc; }

__global__ void __launch_bounds__(32) sig_pair(const float* __restrict__ X,
                                               const float* __restrict__ Y)
{
    __shared__ float4 sY4[NSEQ * 4];      // dY rows, 4 float4 each  (8128 B)
    __shared__ float  sInc[32 * 129];     // skewed inc strip        (16512 B)
    __shared__ float  sBound[2][128];     // strip boundary rows     (1024 B)

    const int task = blockIdx.x;
    const int lane = threadIdx.x;

    // ---- decode task -> (Px, Py, a, b, weight) ----
    const float *Px, *Py;
    int a, b;
    float w;
    if (task < 2 * NTRI) {
        int u = task;
        const float* P = X;
        if (u >= NTRI) { u -= NTRI; P = Y; }
        // entries before row a:  f(a) = a*(129-a)/2 ;  solve f(a) <= u < f(a+1)
        int aa = (int)((129.0f - sqrtf(16641.0f - 8.0f * (float)u)) * 0.5f);
        if (aa < 0) aa = 0;
        if (aa > 63) aa = 63;
        while (aa > 0 && aa * (129 - aa) / 2 > u) --aa;
        while (aa < 63 && (aa + 1) * (128 - aa) / 2 <= u) ++aa;
        a = aa;
        b = aa + (u - aa * (129 - aa) / 2);
        Px = P; Py = P;
        w = (a == b) ? 1.0f : 2.0f;
    } else {
        int u = task - 2 * NTRI;
        a = u >> 6;
        b = u & 63;
        Px = X; Py = Y;
        w = -2.0f;
    }

    const float* Xa = Px + a * 128 * DIM;
    const float* Yb = Py + b * 128 * DIM;

    // ---- stage dY into smem (difference of consecutive Y rows) ----
    #pragma unroll 4
    for (int idx = lane; idx < NSEQ * 4; idx += 32) {
        int j = idx >> 2, q = idx & 3;
        float4 y0 = *(const float4*)(Yb + j * DIM + q * 4);
        float4 y1 = *(const float4*)(Yb + (j + 1) * DIM + q * 4);
        float4 d;
        d.x = y1.x - y0.x; d.y = y1.y - y0.y;
        d.z = y1.z - y0.z; d.w = y1.w - y0.w;
        sY4[idx] = d;
    }
    #pragma unroll
    for (int idx = lane; idx < 256; idx += 32)
        (&sBound[0][0])[idx] = 1.0f;
    __syncwarp();

    const int base = lane * 129;
    float resultK = 0.0f;
    int haveResult = 0;

    for (int s = 0; s < 4; ++s) {
        // ================= GEMM phase: inc strip into smem =================
        const int row = s * 32 + lane;            // inc row this lane owns
        const int rr  = (row < NSEQ) ? row : 0;   // clamp (garbage row unused)
        float4 xa0 = *(const float4*)(Xa + rr * DIM + 0);
        float4 xa1 = *(const float4*)(Xa + rr * DIM + 4);
        float4 xa2 = *(const float4*)(Xa + rr * DIM + 8);
        float4 xa3 = *(const float4*)(Xa + rr * DIM + 12);
        float4 xb0 = *(const float4*)(Xa + (rr + 1) * DIM + 0);
        float4 xb1 = *(const float4*)(Xa + (rr + 1) * DIM + 4);
        float4 xb2 = *(const float4*)(Xa + (rr + 1) * DIM + 8);
        float4 xb3 = *(const float4*)(Xa + (rr + 1) * DIM + 12);
        float4 dx0, dx1, dx2, dx3;
        dx0.x = xb0.x - xa0.x; dx0.y = xb0.y - xa0.y; dx0.z = xb0.z - xa0.z; dx0.w = xb0.w - xa0.w;
        dx1.x = xb1.x - xa1.x; dx1.y = xb1.y - xa1.y; dx1.z = xb1.z - xa1.z; dx1.w = xb1.w - xa1.w;
        dx2.x = xb2.x - xa2.x; dx2.y = xb2.y - xa2.y; dx2.z = xb2.z - xa2.z; dx2.w = xb2.w - xa2.w;
        dx3.x = xb3.x - xa3.x; dx3.y = xb3.y - xa3.y; dx3.z = xb3.z - xa3.z; dx3.w = xb3.w - xa3.w;

        #pragma unroll 2
        for (int j = 0; j < NSEQ; ++j) {
            float4 y0 = sY4[j * 4 + 0];   // broadcast reads (same addr all lanes)
            float4 y1 = sY4[j * 4 + 1];
            float4 y2 = sY4[j * 4 + 2];
            float4 y3 = sY4[j * 4 + 3];
            float d0 = fmaf(dx0.x, y0.x, fmaf(dx0.y, y0.y, fmaf(dx0.z, y0.z, dx0.w * y0.w)));
            float d1 = fmaf(dx1.x, y1.x, fmaf(dx1.y, y1.y, fmaf(dx1.z, y1.z, dx1.w * y1.w)));
            float d2 = fmaf(dx2.x, y2.x, fmaf(dx2.y, y2.y, fmaf(dx2.z, y2.z, dx2.w * y2.w)));
            float d3 = fmaf(dx3.x, y3.x, fmaf(dx3.y, y3.y, fmaf(dx3.z, y3.z, dx3.w * y3.w)));
            // skewed store: DP reads (lane*129 + (t-1)&127) are conflict-free
            sInc[base + ((j + lane) & 127)] = (d0 + d1) + (d2 + d3);
        }
        __syncwarp();

        // ================= DP phase: systolic 32-lane wavefront =============
        const int i = s * 32 + lane + 1;          // G row this lane computes
        const float* bOld = sBound[s & 1];
        float*       bNew = sBound[(s + 1) & 1];
        float kleft = 1.0f;                       // G[i][j-1]
        float kup   = bOld[1];                    // G[i-1][j]   (lane 0 seed)
        float kdiag = 1.0f;                       // G[i-1][j-1]
        const bool storeLane = (lane == 31);
        const bool laneOn    = (i <= NSEQ);

        #pragma unroll 2
        for (int t = 1; t <= NSEQ + 31; ++t) {
            int  j   = t - lane;
            bool act = (j >= 1) && (j <= NSEQ) && laneOn;
            float incv = sInc[base + ((t - 1) & 127)];
            if (j == 1) { kleft = 1.0f; kdiag = 1.0f; }
            float knew = fmaf(kdiag, incv, (kleft + kup) - kdiag);
            if (act) kleft = knew;
            float recv = __shfl_up_sync(0xffffffffu, kleft, 1);
            int   tn   = (t + 1 <= NSEQ) ? (t + 1) : NSEQ;  // uniform -> broadcast LDS
            float bval = bOld[tn];
            kdiag = kup;
            kup   = (lane == 0) ? bval : recv;
            if (storeLane && act) bNew[j] = kleft;
        }
        __syncwarp();

        if (i == NSEQ) { resultK = kleft; haveResult = 1; }   // lane 30, strip 3
    }

    if (haveResult)
        atomicAdd(&g_acc, (double)(w * resultK) * (1.0 / 4096.0));
}

extern "C" void kernel_launch(void* const* d_in, const int* in_sizes, int n_in,
                              void* d_out, int out_size)
{
    const float* X = (const float*)d_in[0];
    const float* Y = (const float*)d_in[1];
    // d_in[2] is n; setup fixes n = 0 (f = 1), which this kernel implements.
    (void)in_sizes; (void)n_in; (void)out_size;

    sig_init<<<1, 1>>>();
    sig_pair<<<NTASK, 32>>>(X, Y);
    sig_fin<<<1, 1>>>((float*)d_out);
}

// round 4
// speedup vs baseline: 1.0034x; 1.0034x over previous
#include <cuda_runtime.h>
#include <math.h>

// Signature-kernel MMD on GB300.  X, Y: (64, 128, 16) fp32, n=0 (f=1). Out: scalar fp32.
// Per pair: inc = dX_a @ dY_b^T (127x127, K=16), Goursat DP
//   G[i][j] = G[i][j-1] + t_j,  t_j = G[i-1][j] + G[i-1][j-1]*(inc[i-1][j-1]-1)
// k(a,b) = G[127][127].  Loss = mean kxx + mean kyy - 2 mean kxy (symmetry-deduped).

#define DIM   16
#define NSEQ  127
#define NTRI  2080      // 64*65/2
#define NTASK 8256      // 2*NTRI + 4096

__device__ float g_part[NTASK];

typedef unsigned long long u64;

__device__ __forceinline__ u64 mul2(u64 a, u64 b) {
    u64 d; asm("mul.rn.f32x2 %0,%1,%2;" : "=l"(d) : "l"(a), "l"(b)); return d;
}
__device__ __forceinline__ u64 fma2(u64 a, u64 b, u64 c) {
    u64 d; asm("fma.rn.f32x2 %0,%1,%2,%3;" : "=l"(d) : "l"(a), "l"(b), "l"(c)); return d;
}
__device__ __forceinline__ u64 add2(u64 a, u64 b) {
    u64 d; asm("add.rn.f32x2 %0,%1,%2;" : "=l"(d) : "l"(a), "l"(b)); return d;
}
__device__ __forceinline__ u64 pack2(float lo, float hi) {
    u64 r; asm("mov.b64 %0,{%1,%2};" : "=l"(r) : "f"(lo), "f"(hi)); return r;
}
__device__ __forceinline__ void unpack2(u64 v, float& lo, float& hi) {
    asm("mov.b64 {%0,%1},%2;" : "=f"(lo), "=f"(hi) : "l"(v));
}

__global__ void sig_fin(float* out) {
    __shared__ double sred[256];
    double s = 0.0;
    for (int i = threadIdx.x; i < NTASK; i += 256) s += (double)g_part[i];
    sred[threadIdx.x] = s;
    __syncthreads();
    for (int k = 128; k > 0; k >>= 1) {
        if (threadIdx.x < k) sred[threadIdx.x] += sred[threadIdx.x + k];
        __syncthreads();
    }
    if (threadIdx.x == 0) out[0] = (float)sred[0];
}

__global__ void __launch_bounds__(32) sig_pair(const float* __restrict__ X,
                                               const float* __restrict__ Y)
{
    __shared__ float4 sY4[NSEQ * 4];      // dY rows (8128 B)
    __shared__ float  sInc[32 * 129];     // inc strip, pitch 129 (16512 B)
    __shared__ float  sBound[2][132];     // strip boundary rows, cols 0..128

    const int task = blockIdx.x;
    const int lane = threadIdx.x;

    // ---- decode task -> (Px, Py, a, b, weight) ----
    const float *Px, *Py;
    int a, b;
    float w;
    if (task < 2 * NTRI) {
        int u = task;
        const float* P = X;
        if (u >= NTRI) { u -= NTRI; P = Y; }
        int aa = (int)((129.0f - sqrtf(16641.0f - 8.0f * (float)u)) * 0.5f);
        if (aa < 0) aa = 0;
        if (aa > 63) aa = 63;
        while (aa > 0 && aa * (129 - aa) / 2 > u) --aa;
        while (aa < 63 && (aa + 1) * (128 - aa) / 2 <= u) ++aa;
        a = aa;
        b = aa + (u - aa * (129 - aa) / 2);
        Px = P; Py = P;
        w = (a == b) ? 1.0f : 2.0f;
    } else {
        int u = task - 2 * NTRI;
        a = u >> 6;
        b = u & 63;
        Px = X; Py = Y;
        w = -2.0f;
    }

    const float* Xa = Px + a * 128 * DIM;
    const float* Yb = Py + b * 128 * DIM;

    // ---- stage dY into smem ----
    #pragma unroll 4
    for (int idx = lane; idx < NSEQ * 4; idx += 32) {
        int j = idx >> 2, q = idx & 3;
        float4 y0 = *(const float4*)(Yb + j * DIM + q * 4);
        float4 y1 = *(const float4*)(Yb + (j + 1) * DIM + q * 4);
        float4 d;
        d.x = y1.x - y0.x; d.y = y1.y - y0.y;
        d.z = y1.z - y0.z; d.w = y1.w - y0.w;
        sY4[idx] = d;
    }
    #pragma unroll
    for (int idx = lane; idx < 264; idx += 32)
        (&sBound[0][0])[idx] = 1.0f;
    __syncwarp();

    const int base = lane * 129;
    float resultK = 0.0f;

    for (int s = 0; s < 4; ++s) {
        // ================= GEMM phase: inc strip (rows s*32+lane) ==========
        const int row = s * 32 + lane;
        const int rr  = (row < NSEQ) ? row : 0;
        u64 dxp[8];
        {
            float4 xa0 = *(const float4*)(Xa + rr * DIM + 0);
            float4 xa1 = *(const float4*)(Xa + rr * DIM + 4);
            float4 xa2 = *(const float4*)(Xa + rr * DIM + 8);
            float4 xa3 = *(const float4*)(Xa + rr * DIM + 12);
            float4 xb0 = *(const float4*)(Xa + (rr + 1) * DIM + 0);
            float4 xb1 = *(const float4*)(Xa + (rr + 1) * DIM + 4);
            float4 xb2 = *(const float4*)(Xa + (rr + 1) * DIM + 8);
            float4 xb3 = *(const float4*)(Xa + (rr + 1) * DIM + 12);
            dxp[0] = pack2(xb0.x - xa0.x, xb0.y - xa0.y);
            dxp[1] = pack2(xb0.z - xa0.z, xb0.w - xa0.w);
            dxp[2] = pack2(xb1.x - xa1.x, xb1.y - xa1.y);
            dxp[3] = pack2(xb1.z - xa1.z, xb1.w - xa1.w);
            dxp[4] = pack2(xb2.x - xa2.x, xb2.y - xa2.y);
            dxp[5] = pack2(xb2.z - xa2.z, xb2.w - xa2.w);
            dxp[6] = pack2(xb3.x - xa3.x, xb3.y - xa3.y);
            dxp[7] = pack2(xb3.z - xa3.z, xb3.w - xa3.w);
        }

        #pragma unroll 4
        for (int j = 0; j < NSEQ; ++j) {
            const ulonglong2* yp = (const ulonglong2*)&sY4[j * 4];
            ulonglong2 y01 = yp[0];   // LDS.128, broadcast (uniform addr)
            ulonglong2 y23 = yp[1];
            ulonglong2 y45 = yp[2];
            ulonglong2 y67 = yp[3];
            u64 a0 = mul2(dxp[0], y01.x);
            u64 a1 = mul2(dxp[1], y01.y);
            u64 a2 = mul2(dxp[2], y23.x);
            u64 a3 = mul2(dxp[3], y23.y);
            a0 = fma2(dxp[4], y45.x, a0);
            a1 = fma2(dxp[5], y45.y, a1);
            a2 = fma2(dxp[6], y67.x, a2);
            a3 = fma2(dxp[7], y67.y, a3);
            u64 s01 = add2(a0, a1);
            u64 s23 = add2(a2, a3);
            u64 st  = add2(s01, s23);
            float lo, hi; unpack2(st, lo, hi);
            sInc[base + j] = lo + hi;
        }
        sInc[base + 127] = 0.0f;   // pad col (block 31, c=3) — deterministic
        __syncwarp();

        // ================= DP phase: W=4 column-blocked systolic ============
        const int  i      = s * 32 + lane + 1;     // G row owned by this lane
        const bool laneOn = (i <= NSEQ);
        const float* bOld = sBound[s & 1];
        float*       bNew = sBound[(s + 1) & 1];
        const bool isLast   = (lane == 31) && laneOn;
        const bool isResult = (i == NSEQ);         // strip 3, lane 30

        // p0..p3: prev-row values at cols cb+1..cb+4 ; pm: col cb ; kprev: G[i][cb]
        float p0, p1, p2, p3, pm = 1.0f, kprev = 1.0f;
        {   // lane 0 prologue (uniform loads, broadcast)
            float q0 = bOld[1], q1 = bOld[2], q2 = bOld[3], q3 = bOld[4];
            p0 = q0; p1 = q1; p2 = q2; p3 = q3;    // only lane 0's values matter
        }

        #pragma unroll 2
        for (int m = 0; m < 63; ++m) {
            int  bb  = m - lane;                   // this lane's block index
            bool act = (bb >= 0) && (bb <= 31) && laneOn;
            if (bb == 0) { pm = 1.0f; kprev = 1.0f; }
            int bc = bb < 0 ? 0 : (bb > 31 ? 31 : bb);
            int cb = 4 * bc;

            const float* ip = sInc + base + cb;    // bank (4m-3*lane+k)%32: conflict-free
            float i0 = ip[0], i1 = ip[1], i2 = ip[2], i3 = ip[3];

            float t0 = fmaf(pm, i0, p0 - pm);
            float t1 = fmaf(p0, i1, p1 - p0);
            float t2 = fmaf(p1, i2, p2 - p1);
            float t3 = fmaf(p2, i3, p3 - p2);
            float k0 = kprev + t0;
            float k1 = k0 + t1;
            float k2 = k1 + t2;
            float k3 = k2 + t3;
            if (act) kprev = k3;
            if (isResult && bb == 31) resultK = k2;          // j = 127
            if (isLast && act) {                             // boundary row for next strip
                bNew[cb + 1] = k0;
                bNew[cb + 2] = k1;
                bNew[cb + 3] = k2;
                if (cb < 124) bNew[cb + 4] = k3;             // skip phantom col 128
            }

            // hand k-block to lane+1 (it processes this block next iteration)
            float r0 = __shfl_up_sync(0xffffffffu, k0, 1);
            float r1 = __shfl_up_sync(0xffffffffu, k1, 1);
            float r2 = __shfl_up_sync(0xffffffffu, k2, 1);
            float r3 = __shfl_up_sync(0xffffffffu, k3, 1);

            // lane 0's next block comes from the boundary row (uniform loads)
            int mn = (m + 1 < 31) ? (m + 1) : 31;
            float nq0 = bOld[4 * mn + 1], nq1 = bOld[4 * mn + 2];
            float nq2 = bOld[4 * mn + 3], nq3 = bOld[4 * mn + 4];

            pm = p3;
            p0 = (lane == 0) ? nq0 : r0;
            p1 = (lane == 0) ? nq1 : r1;
            p2 = (lane == 0) ? nq2 : r2;
            p3 = (lane == 0) ? nq3 : r3;
        }
        __syncwarp();
    }

    if (lane == 30)
        g_part[task] = w * resultK * (1.0f / 4096.0f);
}

extern "C" void kernel_launch(void* const* d_in, const int* in_sizes, int n_in,
                              void* d_out, int out_size)
{
    const float* X = (const float*)d_in[0];
    const float* Y = (const float*)d_in[1];
    (void)in_sizes; (void)n_in; (void)out_size;

    sig_pair<<<NTASK, 32>>>(X, Y);
    sig_fin<<<1, 256>>>((float*)d_out);
}

// round 5
// speedup vs baseline: 1.0093x; 1.0059x over previous
#include <cuda_runtime.h>
#include <math.h>

// Signature-kernel MMD on GB300.  X, Y: (64, 128, 16) fp32, n=0 (f=1). Out: scalar fp32.
// Per pair: inc = dX_a @ dY_b^T (127x127, K=16), Goursat DP
//   G[i][j] = G[i][j-1] + t_j,  t_j = G[i-1][j] + G[i-1][j-1]*(inc[i-1][j-1]-1)
// k(a,b) = G[127][127].  Loss = mean kxx + mean kyy - 2 mean kxy (symmetry-deduped).
// Single fused kernel: last block reduces g_part -> out (keeps ncu on the hot kernel).

#define DIM   16
#define NSEQ  127
#define NTRI  2080      // 64*65/2
#define NTASK 8256      // 2*NTRI + 4096

__device__ float g_part[NTASK];
__device__ unsigned int g_count;          // zero-init; finalizer resets to 0

typedef unsigned long long u64;

__device__ __forceinline__ u64 mul2(u64 a, u64 b) {
    u64 d; asm("mul.rn.f32x2 %0,%1,%2;" : "=l"(d) : "l"(a), "l"(b)); return d;
}
__device__ __forceinline__ u64 fma2(u64 a, u64 b, u64 c) {
    u64 d; asm("fma.rn.f32x2 %0,%1,%2,%3;" : "=l"(d) : "l"(a), "l"(b), "l"(c)); return d;
}
__device__ __forceinline__ u64 add2(u64 a, u64 b) {
    u64 d; asm("add.rn.f32x2 %0,%1,%2;" : "=l"(d) : "l"(a), "l"(b)); return d;
}
__device__ __forceinline__ u64 pack2(float lo, float hi) {
    u64 r; asm("mov.b64 %0,{%1,%2};" : "=l"(r) : "f"(lo), "f"(hi)); return r;
}
__device__ __forceinline__ void unpack2(u64 v, float& lo, float& hi) {
    asm("mov.b64 {%0,%1},%2;" : "=f"(lo), "=f"(hi) : "l"(v));
}

__global__ void __launch_bounds__(32) sig_pair(const float* __restrict__ X,
                                               const float* __restrict__ Y,
                                               float* __restrict__ out)
{
    __shared__ float4 sY4[NSEQ * 4];        // dY rows (8128 B)
    __shared__ float  sInc[32 * 129];       // inc strip, pitch 129 (16512 B)
    __shared__ float4 sBnd[2][33];          // boundary, shifted: sBnd[*][b].k = G[.][4b+1+k]

    const int task = blockIdx.x;
    const int lane = threadIdx.x;

    // ---- decode task -> (Px, Py, a, b, weight) ----
    const float *Px, *Py;
    int a, b;
    float w;
    if (task < 2 * NTRI) {
        int u = task;
        const float* P = X;
        if (u >= NTRI) { u -= NTRI; P = Y; }
        int aa = (int)((129.0f - sqrtf(16641.0f - 8.0f * (float)u)) * 0.5f);
        if (aa < 0) aa = 0;
        if (aa > 63) aa = 63;
        while (aa > 0 && aa * (129 - aa) / 2 > u) --aa;
        while (aa < 63 && (aa + 1) * (128 - aa) / 2 <= u) ++aa;
        a = aa;
        b = aa + (u - aa * (129 - aa) / 2);
        Px = P; Py = P;
        w = (a == b) ? 1.0f : 2.0f;
    } else {
        int u = task - 2 * NTRI;
        a = u >> 6;
        b = u & 63;
        Px = X; Py = Y;
        w = -2.0f;
    }

    const float* Xa = Px + a * 128 * DIM;
    const float* Yb = Py + b * 128 * DIM;

    // ---- stage dY into smem ----
    #pragma unroll 4
    for (int idx = lane; idx < NSEQ * 4; idx += 32) {
        int j = idx >> 2, q = idx & 3;
        float4 y0 = *(const float4*)(Yb + j * DIM + q * 4);
        float4 y1 = *(const float4*)(Yb + (j + 1) * DIM + q * 4);
        float4 d;
        d.x = y1.x - y0.x; d.y = y1.y - y0.y;
        d.z = y1.z - y0.z; d.w = y1.w - y0.w;
        sY4[idx] = d;
    }
    {   // boundary rows init to 1.0 (row 0 of G)
        float* bp = (float*)&sBnd[0][0];
        #pragma unroll
        for (int idx = lane; idx < 264; idx += 32) bp[idx] = 1.0f;
    }
    __syncwarp();

    const int base = lane * 129;
    float resultK = 0.0f;

    for (int s = 0; s < 4; ++s) {
        // ================= GEMM phase: inc strip (rows s*32+lane) ==========
        const int row = s * 32 + lane;
        const int rr  = (row < NSEQ) ? row : 0;
        u64 dxp[8];
        {
            float4 xa0 = *(const float4*)(Xa + rr * DIM + 0);
            float4 xa1 = *(const float4*)(Xa + rr * DIM + 4);
            float4 xa2 = *(const float4*)(Xa + rr * DIM + 8);
            float4 xa3 = *(const float4*)(Xa + rr * DIM + 12);
            float4 xb0 = *(const float4*)(Xa + (rr + 1) * DIM + 0);
            float4 xb1 = *(const float4*)(Xa + (rr + 1) * DIM + 4);
            float4 xb2 = *(const float4*)(Xa + (rr + 1) * DIM + 8);
            float4 xb3 = *(const float4*)(Xa + (rr + 1) * DIM + 12);
            dxp[0] = pack2(xb0.x - xa0.x, xb0.y - xa0.y);
            dxp[1] = pack2(xb0.z - xa0.z, xb0.w - xa0.w);
            dxp[2] = pack2(xb1.x - xa1.x, xb1.y - xa1.y);
            dxp[3] = pack2(xb1.z - xa1.z, xb1.w - xa1.w);
            dxp[4] = pack2(xb2.x - xa2.x, xb2.y - xa2.y);
            dxp[5] = pack2(xb2.z - xa2.z, xb2.w - xa2.w);
            dxp[6] = pack2(xb3.x - xa3.x, xb3.y - xa3.y);
            dxp[7] = pack2(xb3.z - xa3.z, xb3.w - xa3.w);
        }

        #pragma unroll 4
        for (int j = 0; j < NSEQ; ++j) {
            const ulonglong2* yp = (const ulonglong2*)&sY4[j * 4];
            ulonglong2 y01 = yp[0];   // LDS.128, uniform -> broadcast
            ulonglong2 y23 = yp[1];
            ulonglong2 y45 = yp[2];
            ulonglong2 y67 = yp[3];
            u64 a0 = mul2(dxp[0], y01.x);
            u64 a1 = mul2(dxp[1], y01.y);
            u64 a2 = mul2(dxp[2], y23.x);
            u64 a3 = mul2(dxp[3], y23.y);
            a0 = fma2(dxp[4], y45.x, a0);
            a1 = fma2(dxp[5], y45.y, a1);
            a2 = fma2(dxp[6], y67.x, a2);
            a3 = fma2(dxp[7], y67.y, a3);
            u64 s01 = add2(a0, a1);
            u64 s23 = add2(a2, a3);
            u64 st  = add2(s01, s23);
            float lo, hi; unpack2(st, lo, hi);
            sInc[base + j] = lo + hi;     // banks (lane*129+j)%32: conflict-free
        }
        sInc[base + 127] = 0.0f;          // pad col (block 31, k=3) — deterministic
        __syncwarp();

        // ================= DP phase: W=4 column-blocked systolic ============
        const int  i      = s * 32 + lane + 1;     // G row owned by this lane
        const bool laneOn = (i <= NSEQ);
        const float4* bOld = sBnd[s & 1];
        float4*       bNew = sBnd[(s + 1) & 1];
        const bool isLast   = (lane == 31) && laneOn;
        const bool isResult = (i == NSEQ);         // strip 3, lane 30

        // p0..p3: prev-row cols 4bb+1..4bb+4 ; pm: col 4bb ; kprev: G[i][4bb]
        float p0, p1, p2, p3, pm = 1.0f, kprev = 1.0f;
        {
            float4 q = bOld[0];                    // cols 1..4 (lane 0 seed)
            p0 = q.x; p1 = q.y; p2 = q.z; p3 = q.w;
        }

        #pragma unroll 2
        for (int m = 0; m < 63; ++m) {
            int  bb  = m - lane;                   // this lane's block index
            bool act = (bb >= 0) && (bb <= 31) && laneOn;
            if (bb == 0) { pm = 1.0f; kprev = 1.0f; }
            int bc = bb < 0 ? 0 : (bb > 31 ? 31 : bb);
            int cb = 4 * bc;

            const float* ip = sInc + base + cb;    // 4x LDS.32, conflict-free
            float i0 = ip[0], i1 = ip[1], i2 = ip[2], i3 = ip[3];

            float t0 = fmaf(pm, i0, p0 - pm);
            float t1 = fmaf(p0, i1, p1 - p0);
            float t2 = fmaf(p1, i2, p2 - p1);
            float t3 = fmaf(p2, i3, p3 - p2);
            float k0 = kprev + t0;
            float k1 = k0 + t1;
            float k2 = k1 + t2;
            float k3 = k2 + t3;
            if (act) kprev = k3;
            if (isResult && bb == 31) resultK = k2;          // j = 127
            if (isLast && act)                               // 1x STS.128
                bNew[bc] = make_float4(k0, k1, k2, k3);

            // hand k-block to lane+1 (it processes this block next iteration)
            float r0 = __shfl_up_sync(0xffffffffu, k0, 1);
            float r1 = __shfl_up_sync(0xffffffffu, k1, 1);
            float r2 = __shfl_up_sync(0xffffffffu, k2, 1);
            float r3 = __shfl_up_sync(0xffffffffu, k3, 1);

            // lane 0's next block from boundary: 1x uniform LDS.128 (broadcast)
            int mn = (m + 1 < 31) ? (m + 1) : 31;
            float4 nq = bOld[mn];

            pm = p3;
            p0 = (lane == 0) ? nq.x : r0;
            p1 = (lane == 0) ? nq.y : r1;
            p2 = (lane == 0) ? nq.z : r2;
            p3 = (lane == 0) ? nq.w : r3;
        }
        __syncwarp();
    }

    if (lane == 30)
        g_part[task] = w * resultK * (1.0f / 4096.0f);

    // ---- last block reduces all partials -> out ----
    __threadfence();
    unsigned int done = 0;
    if (lane == 0) done = atomicAdd(&g_count, 1u);
    done = __shfl_sync(0xffffffffu, done, 0);
    if (done == NTASK - 1) {
        __threadfence();
        double sum = 0.0;
        #pragma unroll 4
        for (int i = lane; i < NTASK; i += 32) sum += (double)g_part[i];
        #pragma unroll
        for (int off = 16; off > 0; off >>= 1)
            sum += __shfl_down_sync(0xffffffffu, sum, off);
        if (lane == 0) {
            out[0] = (float)sum;
            atomicExch(&g_count, 0u);     // reset for next graph replay
        }
    }
}

extern "C" void kernel_launch(void* const* d_in, const int* in_sizes, int n_in,
                              void* d_out, int out_size)
{
    const float* X = (const float*)d_in[0];
    const float* Y = (const float*)d_in[1];
    (void)in_sizes; (void)n_in; (void)out_size;

    // Ask for the maximum shared-memory carveout so 8 blocks (25.7 KB each)
    // fit per SM. Host-side attribute, idempotent, legal during capture.
    cudaFuncSetAttribute(sig_pair, cudaFuncAttributePreferredSharedMemoryCarveout, 100);

    sig_pair<<<NTASK, 32>>>(X, Y, (float*)d_out);
}

// round 8
// speedup vs baseline: 1.6786x; 1.6632x over previous
#include <cuda_runtime.h>
#include <math.h>

// Signature-kernel MMD on GB300.  X, Y: (64, 128, 16) fp32, n=0 (f=1). Out: scalar fp32.
// inc = dX_a @ dY_b^T (127x127, K=16);  G[i][j] = G[i][j-1] + G[i-1][j] + G[i-1][j-1]*(inc[i-1][j-1]-1)
// k(a,b) = G[127][127].  Loss = mean kxx + mean kyy - 2 mean kxy (symmetry-deduped).
//
// R6 design: one warp per pair; lane l owns G rows 4l+1..4l+4 and marches columns
// (single systolic pass, no strips). inc produced 8 columns at a time into a
// 40-column smem ring (column-major, pitch 128 -> bank = 4*lane, conflict-free
// for both STS.128 and LDS.128). Lane l computes exactly the inc rows it later
// consumes -> no cross-lane smem dependency, no syncs. dX/dY precomputed to
// global scratch; dY read as uniform LDG (no reuse within a pair).

#define DIM   16
#define NTRI  2080      // 64*65/2
#define NTASK 8256      // 2*NTRI + 4096
#define RING  40

__device__ float g_dX[64 * 128 * DIM];   // row 127 zero-filled
__device__ float g_dY[64 * 128 * DIM];
__device__ float g_part[NTASK];
__device__ unsigned int g_count;         // zero-init; finalizer resets

typedef unsigned long long u64;

__device__ __forceinline__ u64 mul2(u64 a, u64 b) {
    u64 d; asm("mul.rn.f32x2 %0,%1,%2;" : "=l"(d) : "l"(a), "l"(b)); return d;
}
__device__ __forceinline__ u64 fma2(u64 a, u64 b, u64 c) {
    u64 d; asm("fma.rn.f32x2 %0,%1,%2,%3;" : "=l"(d) : "l"(a), "l"(b), "l"(c)); return d;
}
__device__ __forceinline__ u64 add2(u64 a, u64 b) {
    u64 d; asm("add.rn.f32x2 %0,%1,%2;" : "=l"(d) : "l"(a), "l"(b)); return d;
}
__device__ __forceinline__ float hsum2(u64 v) {
    float lo, hi; asm("mov.b64 {%0,%1},%2;" : "=f"(lo), "=f"(hi) : "l"(v));
    return lo + hi;
}

__global__ void sig_prep(const float* __restrict__ X, const float* __restrict__ Y) {
    int idx = blockIdx.x * blockDim.x + threadIdx.x;   // over 64*128*16
    if (idx >= 64 * 128 * DIM) return;
    int d = idx & (DIM - 1);
    int i = (idx >> 4) & 127;
    int a = idx >> 11;
    float vx = 0.0f, vy = 0.0f;
    if (i < 127) {
        int p = a * 128 * DIM + i * DIM + d;
        vx = X[p + DIM] - X[p];
        vy = Y[p + DIM] - Y[p];
    }
    g_dX[idx] = vx;
    g_dY[idx] = vy;
}

__global__ void __launch_bounds__(32, 10) sig_pair(float* __restrict__ out)
{
    __shared__ float sRing[RING * 128];    // 20480 B; col-major, pitch 128 floats

    const int task = blockIdx.x;
    const int lane = threadIdx.x;

    // ---- decode task -> (dxP, dyP, weight) ----
    const float *dxP, *dyP;
    float w;
    if (task < 2 * NTRI) {
        int u = task;
        const float* P = g_dX;
        if (u >= NTRI) { u -= NTRI; P = g_dY; }
        int aa = (int)((129.0f - sqrtf(16641.0f - 8.0f * (float)u)) * 0.5f);
        if (aa < 0) aa = 0;
        if (aa > 63) aa = 63;
        while (aa > 0 && aa * (129 - aa) / 2 > u) --aa;
        while (aa < 63 && (aa + 1) * (128 - aa) / 2 <= u) ++aa;
        int b = aa + (u - aa * (129 - aa) / 2);
        dxP = P + aa * 128 * DIM;
        dyP = P + b  * 128 * DIM;
        w = (aa == b) ? 1.0f : 2.0f;
    } else {
        int u = task - 2 * NTRI;
        dxP = g_dX + (u >> 6) * 128 * DIM;
        dyP = g_dY + (u & 63) * 128 * DIM;
        w = -2.0f;
    }

    // ---- lane-private dX rows 4l..4l+3 packed as f32x2 (row 127 is zeros) ----
    u64 dxp[32];
    #pragma unroll
    for (int r = 0; r < 4; ++r) {
        const u64* p = (const u64*)(dxP + (4 * lane + r) * DIM);
        #pragma unroll
        for (int k = 0; k < 8; ++k) dxp[r * 8 + k] = p[k];
    }

    const int rbase = 4 * lane;            // this lane's 16B slice of each ring column

    // ---- produce 8 inc columns (col0..col0+7) into ring slots slot0..slot0+7 ----
    #define PRODUCE8(col0, slot0) do {                                         \
        const float* dy = dyP + (col0) * DIM;                                  \
        _Pragma("unroll")                                                      \
        for (int jj = 0; jj < 8; ++jj) {                                       \
            const u64* y = (const u64*)dy;                                     \
            u64 y0 = y[0], y1 = y[1], y2 = y[2], y3 = y[3];                    \
            u64 y4 = y[4], y5 = y[5], y6 = y[6], y7 = y[7];                    \
            float dd[4];                                                       \
            _Pragma("unroll")                                                  \
            for (int r = 0; r < 4; ++r) {                                      \
                u64 ta = mul2(dxp[r * 8 + 0], y0);                             \
                u64 tb = mul2(dxp[r * 8 + 1], y1);                             \
                ta = fma2(dxp[r * 8 + 2], y2, ta);                             \
                tb = fma2(dxp[r * 8 + 3], y3, tb);                             \
                ta = fma2(dxp[r * 8 + 4], y4, ta);                             \
                tb = fma2(dxp[r * 8 + 5], y5, tb);                             \
                ta = fma2(dxp[r * 8 + 6], y6, ta);                             \
                tb = fma2(dxp[r * 8 + 7], y7, tb);                             \
                dd[r] = hsum2(add2(ta, tb));                                   \
            }                                                                  \
            *(float4*)(sRing + ((slot0) + jj) * 128 + rbase) =                 \
                make_float4(dd[0], dd[1], dd[2], dd[3]);                       \
            dy += DIM;                                                         \
        }                                                                      \
    } while (0)

    // ---- DP state: lane l holds G rows 4l+1..4l+4 at current column ----
    float gr0 = 1.0f, gr1 = 1.0f, gr2 = 1.0f, gr3 = 1.0f;
    float up = 1.0f, up_prev = 1.0f;       // G[4l][j], G[4l][j-1]
    int rj = (lane == 0) ? 0 : (RING - lane);   // slot of col (m - lane) mod RING
    int m = 0;

    #define DP_ITER do {                                                       \
        bool act = ((unsigned)(m - lane) <= 126u);                             \
        float4 iv = *(const float4*)(sRing + rj * 128 + rbase);                \
        float u0 = fmaf(up_prev, iv.x, gr0 - up_prev);                         \
        float u1 = fmaf(gr0, iv.y, gr1 - gr0);                                 \
        float u2 = fmaf(gr1, iv.z, gr2 - gr1);                                 \
        float u3 = fmaf(gr2, iv.w, gr3 - gr2);                                 \
        float n0 = u0 + up;                                                    \
        float n1 = u1 + n0;                                                    \
        float n2 = u2 + n1;                                                    \
        float n3 = u3 + n2;                                                    \
        if (act) { gr0 = n0; gr1 = n1; gr2 = n2; gr3 = n3; up_prev = up; }     \
        float snd = __shfl_up_sync(0xffffffffu, gr3, 1);                       \
        up = (lane == 0) ? 1.0f : snd;                                         \
        rj = (rj + 1 == RING) ? 0 : rj + 1;                                    \
        ++m;                                                                   \
    } while (0)

    // ---- interleaved schedule: consume 8, produce 8 (ring-overwrite safe) ----
    PRODUCE8(0, 0);                        // cols 0..7
    int slotc = 8;
    for (int c = 1; c < 16; ++c) {
        #pragma unroll
        for (int k = 0; k < 8; ++k) DP_ITER;
        PRODUCE8(8 * c, slotc);            // chunk base slots: 8,16,24,32,0,8,...
        slotc += 8; if (slotc >= RING) slotc -= RING;
    }
    #pragma unroll 2
    for (int t = 0; t < 38; ++t) DP_ITER;  // m: 120..157

    // lane 31 rows 125..128 -> gr2 holds G[127][127]
    if (lane == 31)
        g_part[task] = w * gr2 * (1.0f / 4096.0f);

    // ---- last block reduces all partials -> out ----
    __threadfence();
    unsigned int done = 0;
    if (lane == 0) done = atomicAdd(&g_count, 1u);
    done = __shfl_sync(0xffffffffu, done, 0);
    if (done == NTASK - 1) {
        __threadfence();
        double sum = 0.0;
        #pragma unroll 4
        for (int i = lane; i < NTASK; i += 32) sum += (double)g_part[i];
        #pragma unroll
        for (int off = 16; off > 0; off >>= 1)
            sum += __shfl_down_sync(0xffffffffu, sum, off);
        if (lane == 0) {
            out[0] = (float)sum;
            atomicExch(&g_count, 0u);      // reset for next graph replay
        }
    }
}

extern "C" void kernel_launch(void* const* d_in, const int* in_sizes, int n_in,
                              void* d_out, int out_size)
{
    const float* X = (const float*)d_in[0];
    const float* Y = (const float*)d_in[1];
    (void)in_sizes; (void)n_in; (void)out_size;

    cudaFuncSetAttribute(sig_pair, cudaFuncAttributePreferredSharedMemoryCarveout, 100);

    sig_prep<<<(64 * 128 * DIM + 255) / 256, 256>>>(X, Y);
    sig_pair<<<NTASK, 32>>>((float*)d_out);
}